// round 6
// baseline (speedup 1.0000x reference)
#include <cuda_runtime.h>
#include <cuda_fp16.h>
#include <cuda_bf16.h>
#include <cstdint>

// ---------------- problem constants ----------------
#define N_NODES 100000
#define N_EDGES 3200000
#define F_IN    512
#define HEADS   8
#define HID     8
#define C1      64
#define NCLS    16
#define TOTE    (N_EDGES + N_NODES)
#define NB1024  ((N_NODES + 1023) / 1024)

// GEMM1 tiling (mma.sync m16n8k16 bf16)
#define GM_M   128
#define GK     64
#define NCH    (F_IN / GK)      // 8
#define SAST   72               // padded k-stride (bf16 elems) -> conflict-free frags

// ---------------- device scratch ----------------
__device__ __half g_h1  [(size_t)N_NODES * C1];
__device__ float  g_hact[(size_t)N_NODES * C1];
__device__ float  g_as1 [(size_t)N_NODES * HEADS];
__device__ float  g_ad1 [(size_t)N_NODES * HEADS];
__device__ __half g_h2  [(size_t)N_NODES * NCLS];
__device__ float  g_as2 [N_NODES];
__device__ float  g_ad2 [N_NODES];
__device__ int    g_rowptr[N_NODES + 1];
__device__ int    g_cnt [N_NODES];
__device__ int    g_woff[N_NODES];
__device__ int    g_srcs[TOTE];
__device__ int    g_part [128];
__device__ int    g_part2[128];
__device__ int    g_is64;
// W1 split, transposed [n][k], padded: per chunk 64 x 72 bf16
__device__ __align__(16) __nv_bfloat16 g_Bh[NCH][64 * SAST];
__device__ __align__(16) __nv_bfloat16 g_Bl[NCH][64 * SAST];

// ---------------- helpers ----------------
__device__ __forceinline__ float leaky02(float x) { return fmaxf(x, 0.2f * x); }

__device__ __forceinline__ long long load_idx(const void* p, long long i, int is64) {
    return is64 ? ((const long long*)p)[i] : (long long)((const int*)p)[i];
}

__device__ __forceinline__ void mma16816(float* c,
                                         uint32_t a0, uint32_t a1, uint32_t a2, uint32_t a3,
                                         uint32_t b0, uint32_t b1) {
    asm volatile(
        "mma.sync.aligned.m16n8k16.row.col.f32.bf16.bf16.f32 "
        "{%0,%1,%2,%3}, {%4,%5,%6,%7}, {%8,%9}, {%0,%1,%2,%3};"
        : "+f"(c[0]), "+f"(c[1]), "+f"(c[2]), "+f"(c[3])
        : "r"(a0), "r"(a1), "r"(a2), "r"(a3), "r"(b0), "r"(b1));
}

// ---------------- dtype probe ----------------
__global__ void probe_k(const void* ei) {
    __shared__ int s_bad;
    if (threadIdx.x == 0) s_bad = 0;
    __syncthreads();
    const long long* p = (const long long*)ei;
    for (int i = threadIdx.x; i < 1024; i += blockDim.x) {
        long long v = p[i];
        if ((v >> 32) != 0) s_bad = 1;
    }
    __syncthreads();
    if (threadIdx.x == 0) g_is64 = (s_bad == 0) ? 1 : 0;
}

// ---------------- W1 split + transpose (once, tiny) ----------------
__global__ void wsplit_k(const float* __restrict__ W) {
    int t = blockIdx.x * blockDim.x + threadIdx.x;
    if (t >= F_IN * C1) return;
    int k = t >> 6;          // 0..511
    int n = t & 63;
    float x = W[t];          // W[k][n]
    __nv_bfloat16 h = __float2bfloat16(x);
    __nv_bfloat16 l = __float2bfloat16(x - __bfloat162float(h));
    int c = k >> 6, kk = k & 63;
    g_Bh[c][n * SAST + kk] = h;
    g_Bl[c][n * SAST + kk] = l;
}

// ---------------- GEMM1 via HMMA (split-bf16) + fused attn coefs ----------------
// dyn smem: Ah[128*72] | Al[128*72] | Bh[64*72] | Bl[64*72]  (bf16)
#define SM_AH 0
#define SM_AL (128 * SAST)
#define SM_BH (2 * 128 * SAST)
#define SM_BL (2 * 128 * SAST + 64 * SAST)
#define SM_ELL (2 * 128 * SAST + 2 * 64 * SAST)   // 27648 bf16 = 55296 B

__global__ __launch_bounds__(256) void gemm1_k(const float* __restrict__ X,
                                               const float* __restrict__ asw,
                                               const float* __restrict__ adw) {
    extern __shared__ __nv_bfloat16 sm[];
    __nv_bfloat16* Ah = sm + SM_AH;
    __nv_bfloat16* Al = sm + SM_AL;
    __nv_bfloat16* Bh = sm + SM_BH;
    __nv_bfloat16* Bl = sm + SM_BL;

    const int tid  = threadIdx.x;
    const int wid  = tid >> 5;
    const int lane = tid & 31;
    const int m0   = blockIdx.x * GM_M;

    const int srow = tid >> 1;            // staging row 0..127
    const int skh  = (tid & 1) * 32;      // staging k-half
    const bool rvalid = (m0 + srow) < N_NODES;

    const int g   = lane >> 2;            // groupID
    const int tig = lane & 3;

    float acc[8][4];
#pragma unroll
    for (int nt = 0; nt < 8; nt++)
#pragma unroll
        for (int j = 0; j < 4; j++) acc[nt][j] = 0.f;

    for (int c = 0; c < NCH; c++) {
        __syncthreads();   // previous iteration's reads done before overwrite
        // ---- stage A chunk: fp32 -> bf16 hi/lo ----
        const float* xp = X + (size_t)(m0 + srow) * F_IN + c * GK + skh;
#pragma unroll
        for (int j = 0; j < 16; j++) {
            float2 xv = rvalid ? *(const float2*)(xp + 2 * j) : make_float2(0.f, 0.f);
            __nv_bfloat162 h2, l2;
            h2.x = __float2bfloat16(xv.x);
            h2.y = __float2bfloat16(xv.y);
            l2.x = __float2bfloat16(xv.x - __bfloat162float(h2.x));
            l2.y = __float2bfloat16(xv.y - __bfloat162float(h2.y));
            int idx = srow * SAST + skh + 2 * j;
            *(__nv_bfloat162*)&Ah[idx] = h2;
            *(__nv_bfloat162*)&Al[idx] = l2;
        }
        // ---- stage B chunk: bulk copy pre-split/transposed images ----
        {
            const float4* sh = (const float4*)g_Bh[c];
            const float4* sl = (const float4*)g_Bl[c];
            float4* dh = (float4*)Bh;
            float4* dl = (float4*)Bl;
            for (int i = tid; i < 1152; i += 256) {
                if (i < 576) dh[i] = sh[i];
                else         dl[i - 576] = sl[i - 576];
            }
        }
        __syncthreads();

        // ---- compute: warp tile 16 x 64, 4 k16 steps, 3 split terms ----
        const int arow = 16 * wid + g;
#pragma unroll
        for (int k16 = 0; k16 < 4; k16++) {
            const int k0 = k16 * 16 + tig * 2;
            uint32_t ah0 = *(const uint32_t*)&Ah[arow * SAST + k0];
            uint32_t ah1 = *(const uint32_t*)&Ah[(arow + 8) * SAST + k0];
            uint32_t ah2 = *(const uint32_t*)&Ah[arow * SAST + k0 + 8];
            uint32_t ah3 = *(const uint32_t*)&Ah[(arow + 8) * SAST + k0 + 8];
            uint32_t al0 = *(const uint32_t*)&Al[arow * SAST + k0];
            uint32_t al1 = *(const uint32_t*)&Al[(arow + 8) * SAST + k0];
            uint32_t al2 = *(const uint32_t*)&Al[arow * SAST + k0 + 8];
            uint32_t al3 = *(const uint32_t*)&Al[(arow + 8) * SAST + k0 + 8];
#pragma unroll
            for (int nt = 0; nt < 8; nt++) {
                const int n = nt * 8 + g;
                uint32_t bh0 = *(const uint32_t*)&Bh[n * SAST + k0];
                uint32_t bh1 = *(const uint32_t*)&Bh[n * SAST + k0 + 8];
                uint32_t bl0 = *(const uint32_t*)&Bl[n * SAST + k0];
                uint32_t bl1 = *(const uint32_t*)&Bl[n * SAST + k0 + 8];
                mma16816(acc[nt], ah0, ah1, ah2, ah3, bh0, bh1);
                mma16816(acc[nt], ah0, ah1, ah2, ah3, bl0, bl1);
                mma16816(acc[nt], al0, al1, al2, al3, bh0, bh1);
            }
        }
    }

    // ---- epilogue: write fp16 h1 + fused a_s / a_d ----
#pragma unroll
    for (int e = 0; e < 2; e++) {
        const int gm = m0 + 16 * wid + g + 8 * e;
        const bool ok = gm < N_NODES;
        float svh[8], dvh[8];
#pragma unroll
        for (int nt = 0; nt < 8; nt++) {
            float cA = acc[nt][2 * e];
            float cB = acc[nt][2 * e + 1];
            const int col = nt * 8 + 2 * tig;
            if (ok)
                *(__half2*)(g_h1 + (size_t)gm * C1 + col) = __floats2half2_rn(cA, cB);
            float sv = cA * __ldg(asw + col) + cB * __ldg(asw + col + 1);
            float dv = cA * __ldg(adw + col) + cB * __ldg(adw + col + 1);
            sv += __shfl_xor_sync(0xffffffffu, sv, 1);
            sv += __shfl_xor_sync(0xffffffffu, sv, 2);
            dv += __shfl_xor_sync(0xffffffffu, dv, 1);
            dv += __shfl_xor_sync(0xffffffffu, dv, 2);
            svh[nt] = sv;
            dvh[nt] = dv;
        }
        if (ok && tig == 0) {
#pragma unroll
            for (int nt = 0; nt < 8; nt++) {
                g_as1[(size_t)gm * 8 + nt] = svh[nt];
                g_ad1[(size_t)gm * 8 + nt] = dvh[nt];
            }
        }
    }
}

// ---------------- CSR build ----------------
__global__ void initcnt_k() {
    int n = blockIdx.x * blockDim.x + threadIdx.x;
    if (n < N_NODES) g_cnt[n] = 1;
}

__global__ void count_k(const void* ei) {
    long long e = (long long)blockIdx.x * blockDim.x + threadIdx.x;
    if (e >= N_EDGES) return;
    int d = (int)load_idx(ei, (long long)N_EDGES + e, g_is64);
    atomicAdd(&g_cnt[d], 1);
}

__global__ void scan1_k() {
    __shared__ int ws[32];
    const int b = blockIdx.x, t = threadIdx.x;
    const int i = b * 1024 + t;
    int v = (i < N_NODES) ? g_cnt[i] : 0;
    const int lane = t & 31, w = t >> 5;
    int x = v;
#pragma unroll
    for (int o = 1; o < 32; o <<= 1) {
        int y = __shfl_up_sync(0xffffffffu, x, o);
        if (lane >= o) x += y;
    }
    if (lane == 31) ws[w] = x;
    __syncthreads();
    if (w == 0) {
        int y = ws[lane];
#pragma unroll
        for (int o = 1; o < 32; o <<= 1) {
            int z = __shfl_up_sync(0xffffffffu, y, o);
            if (lane >= o) y += z;
        }
        ws[lane] = y;
    }
    __syncthreads();
    int off  = (w > 0) ? ws[w - 1] : 0;
    int incl = x + off;
    if (i < N_NODES) g_rowptr[i] = incl - v;
    if (t == 1023) g_part[b] = incl;
}

__global__ void scan2_k() {
    __shared__ int buf[128];
    int t = threadIdx.x;
    buf[t] = (t < NB1024) ? g_part[t] : 0;
    __syncthreads();
#pragma unroll
    for (int o = 1; o < 128; o <<= 1) {
        int y = (t >= o) ? buf[t - o] : 0;
        __syncthreads();
        buf[t] += y;
        __syncthreads();
    }
    g_part2[t] = buf[t];
}

__global__ void scan3_selfloop_k() {
    int b = blockIdx.x, i = b * 1024 + threadIdx.x;
    if (i == 0) g_rowptr[N_NODES] = TOTE;
    if (i >= N_NODES) return;
    int off = (b > 0) ? g_part2[b - 1] : 0;
    int p = g_rowptr[i] + off;
    g_rowptr[i] = p;
    g_srcs[p]   = i;
    g_woff[i]   = p + 1;
}

__global__ void scatter_k(const void* ei) {
    long long e = (long long)blockIdx.x * blockDim.x + threadIdx.x;
    if (e >= N_EDGES) return;
    int is64 = g_is64;
    int s = (int)load_idx(ei, e, is64);
    int d = (int)load_idx(ei, (long long)N_EDGES + e, is64);
    int pos = atomicAdd(&g_woff[d], 1);
    g_srcs[pos] = s;
}

// ---------------- layer1 aggregate ----------------
__global__ void agg1_k(const float* __restrict__ b1) {
    const int gw   = (blockIdx.x * blockDim.x + threadIdx.x) >> 5;
    const int lane = threadIdx.x & 31;
    const int w    = threadIdx.x >> 5;
    __shared__ float sAl [8][8][32];
    __shared__ int   sSrc[8][32];
    __shared__ float sR  [8][8];
    if (gw >= N_NODES) return;
    const int beg = g_rowptr[gw], end = g_rowptr[gw + 1];

    float ad[8];
    {
        float4 u = *(const float4*)(g_ad1 + (size_t)gw * 8);
        float4 v = *(const float4*)(g_ad1 + (size_t)gw * 8 + 4);
        ad[0]=u.x; ad[1]=u.y; ad[2]=u.z; ad[3]=u.w;
        ad[4]=v.x; ad[5]=v.y; ad[6]=v.z; ad[7]=v.w;
    }

    float m[8], s[8];
#pragma unroll
    for (int h = 0; h < 8; h++) { m[h] = -1e30f; s[h] = 0.f; }
    for (int i = beg + lane; i < end; i += 32) {
        int sx = g_srcs[i];
        float4 u = *(const float4*)(g_as1 + (size_t)sx * 8);
        float4 v = *(const float4*)(g_as1 + (size_t)sx * 8 + 4);
        float xs[8] = {u.x, u.y, u.z, u.w, v.x, v.y, v.z, v.w};
#pragma unroll
        for (int h = 0; h < 8; h++) {
            float x  = leaky02(xs[h] + ad[h]);
            float mn = fmaxf(m[h], x);
            s[h] = s[h] * __expf(m[h] - mn) + __expf(x - mn);
            m[h] = mn;
        }
    }
#pragma unroll
    for (int o = 16; o; o >>= 1) {
#pragma unroll
        for (int h = 0; h < 8; h++) {
            float m2 = __shfl_xor_sync(0xffffffffu, m[h], o);
            float s2 = __shfl_xor_sync(0xffffffffu, s[h], o);
            float mn = fmaxf(m[h], m2);
            s[h] = s[h] * __expf(m[h] - mn) + s2 * __expf(m2 - mn);
            m[h] = mn;
        }
    }
    if (lane == 0) {
#pragma unroll
        for (int h = 0; h < 8; h++) sR[w][h] = 1.0f / s[h];
    }
    __syncwarp();

    const int c0 = lane * 2;
    const int hd = lane >> 2;
    float a0 = 0.f, a1 = 0.f;

    for (int chunk = beg; chunk < end; chunk += 32) {
        int i = chunk + lane;
        int sx = gw;
        float e8[8];
        if (i < end) {
            sx = g_srcs[i];
            float4 u = *(const float4*)(g_as1 + (size_t)sx * 8);
            float4 v = *(const float4*)(g_as1 + (size_t)sx * 8 + 4);
            float xs[8] = {u.x, u.y, u.z, u.w, v.x, v.y, v.z, v.w};
#pragma unroll
            for (int h = 0; h < 8; h++)
                e8[h] = __expf(leaky02(xs[h] + ad[h]) - m[h]);
        } else {
#pragma unroll
            for (int h = 0; h < 8; h++) e8[h] = 0.f;
        }
        sSrc[w][lane] = sx;
#pragma unroll
        for (int h = 0; h < 8; h++) sAl[w][h][lane] = e8[h];
        __syncwarp();

        const int ec = min(32, end - chunk);
#pragma unroll 8
        for (int e = 0; e < ec; e++) {
            int   sy = sSrc[w][e];
            float al = sAl[w][hd][e];
            float2 hv = __half22float2(*(const __half2*)(g_h1 + (size_t)sy * C1 + c0));
            a0 += hv.x * al;
            a1 += hv.y * al;
        }
        __syncwarp();
    }

    const float rsh = sR[w][hd];
    float o0 = a0 * rsh + b1[c0];
    float o1 = a1 * rsh + b1[c0 + 1];
    g_hact[(size_t)gw * C1 + c0]     = (o0 > 0.f) ? o0 : (__expf(o0) - 1.0f);
    g_hact[(size_t)gw * C1 + c0 + 1] = (o1 > 0.f) ? o1 : (__expf(o1) - 1.0f);
}

// ---------------- layer2 GEMM + attn coefs ----------------
__global__ void gemm2_attn_k(const float* __restrict__ W2,
                             const float* __restrict__ asrc2,
                             const float* __restrict__ adst2) {
    __shared__ float Xs[16 * 64];
    __shared__ float Ws[64 * 16];
    const int tid = threadIdx.x;
    const int n0  = blockIdx.x * 16;

    ((float4*)Ws)[tid] = ((const float4*)W2)[tid];
    {
        int row = tid >> 4;
        float4 v = make_float4(0.f, 0.f, 0.f, 0.f);
        if (n0 + row < N_NODES)
            v = ((const float4*)(g_hact + (size_t)n0 * C1))[tid];
        ((float4*)Xs)[tid] = v;
    }
    __syncthreads();

    const int r = tid >> 4, c = tid & 15;
    float acc = 0.f;
#pragma unroll
    for (int k = 0; k < 64; k++) acc += Xs[r * 64 + k] * Ws[k * 16 + c];
    const int n = n0 + r;
    if (n < N_NODES) g_h2[(size_t)n * NCLS + c] = __float2half_rn(acc);

    float vs = acc * asrc2[c];
    float vd = acc * adst2[c];
#pragma unroll
    for (int off = 8; off; off >>= 1) {
        vs += __shfl_xor_sync(0xffffffffu, vs, off);
        vd += __shfl_xor_sync(0xffffffffu, vd, off);
    }
    if (c == 0 && n < N_NODES) {
        g_as2[n] = vs;
        g_ad2[n] = vd;
    }
}

// ---------------- layer2 aggregate ----------------
__global__ void agg2_k(const float* __restrict__ b2, float* __restrict__ out) {
    const int gw   = (blockIdx.x * blockDim.x + threadIdx.x) >> 5;
    const int lane = threadIdx.x & 31;
    const int w    = threadIdx.x >> 5;
    __shared__ float sAl [8][32];
    __shared__ int   sSrc[8][32];
    if (gw >= N_NODES) return;
    const int beg = g_rowptr[gw], end = g_rowptr[gw + 1];
    const float adn = g_ad2[gw];

    float m = -1e30f, s = 0.f;
    for (int i = beg + lane; i < end; i += 32) {
        float x  = leaky02(g_as2[g_srcs[i]] + adn);
        float mn = fmaxf(m, x);
        s = s * __expf(m - mn) + __expf(x - mn);
        m = mn;
    }
#pragma unroll
    for (int o = 16; o; o >>= 1) {
        float m2 = __shfl_xor_sync(0xffffffffu, m, o);
        float s2 = __shfl_xor_sync(0xffffffffu, s, o);
        float mn = fmaxf(m, m2);
        s = s * __expf(m - mn) + s2 * __expf(m2 - mn);
        m = mn;
    }
    const float rs = 1.0f / s;

    const int c    = lane & 15;
    const int half = lane >> 4;
    float acc = 0.f;

    for (int chunk = beg; chunk < end; chunk += 32) {
        int i = chunk + lane;
        int sx = gw;
        float e = 0.f;
        if (i < end) {
            sx = g_srcs[i];
            e  = __expf(leaky02(g_as2[sx] + adn) - m);
        }
        sSrc[w][lane] = sx;
        sAl [w][lane] = e;
        __syncwarp();

        const int ec = min(32, end - chunk);
#pragma unroll 8
        for (int e0 = half; e0 < ec; e0 += 2) {
            int   sy = sSrc[w][e0];
            float al = sAl[w][e0];
            acc += __half2float(g_h2[(size_t)sy * NCLS + c]) * al;
        }
        __syncwarp();
    }

    acc += __shfl_down_sync(0xffffffffu, acc, 16);
    if (lane < 16) out[(size_t)gw * NCLS + c] = acc * rs + b2[c];
}

// ---------------- launch ----------------
extern "C" void kernel_launch(void* const* d_in, const int* in_sizes, int n_in,
                              void* d_out, int out_size) {
    const float* x    = (const float*)d_in[0];
    const void*  ei   = d_in[1];
    const float* W1   = (const float*)d_in[2];
    const float* as1w = (const float*)d_in[3];
    const float* ad1w = (const float*)d_in[4];
    const float* b1   = (const float*)d_in[5];
    const float* W2   = (const float*)d_in[6];
    const float* as2w = (const float*)d_in[7];
    const float* ad2w = (const float*)d_in[8];
    const float* b2   = (const float*)d_in[9];
    float* out = (float*)d_out;

    const int smem = SM_ELL * 2;   // 55296 bytes
    cudaFuncSetAttribute(gemm1_k, cudaFuncAttributeMaxDynamicSharedMemorySize, smem);

    probe_k<<<1, 256>>>(ei);
    initcnt_k<<<(N_NODES + 255) / 256, 256>>>();
    wsplit_k<<<(F_IN * C1 + 255) / 256, 256>>>(W1);
    // launch index 3 -> ncu capture slot
    gemm1_k<<<(N_NODES + GM_M - 1) / GM_M, 256, smem>>>(x, as1w, ad1w);

    count_k<<<(N_EDGES + 255) / 256, 256>>>(ei);
    scan1_k<<<NB1024, 1024>>>();
    scan2_k<<<1, 128>>>();
    scan3_selfloop_k<<<NB1024, 1024>>>();
    scatter_k<<<(N_EDGES + 255) / 256, 256>>>(ei);

    agg1_k<<<(N_NODES + 7) / 8, 256>>>(b1);
    gemm2_attn_k<<<(N_NODES + 15) / 16, 256>>>(W2, as2w, ad2w);
    agg2_k<<<(N_NODES + 7) / 8, 256>>>(b2, out);
}

// round 7
// speedup vs baseline: 1.1803x; 1.1803x over previous
#include <cuda_runtime.h>
#include <cuda_fp16.h>
#include <cstdint>

// ---------------- problem constants ----------------
#define N_NODES 100000
#define N_EDGES 3200000
#define F_IN    512
#define HEADS   8
#define HID     8
#define C1      64
#define NCLS    16
#define TOTE    (N_EDGES + N_NODES)
#define NB1024  ((N_NODES + 1023) / 1024)

// ---------------- device scratch ----------------
__device__ __half g_h1  [(size_t)N_NODES * C1];
__device__ float  g_hact[(size_t)N_NODES * C1];
__device__ float  g_as1 [(size_t)N_NODES * HEADS];
__device__ float  g_ad1 [(size_t)N_NODES * HEADS];
__device__ __half g_h2  [(size_t)N_NODES * NCLS];
__device__ float  g_as2 [N_NODES];
__device__ float  g_ad2 [N_NODES];
__device__ int    g_rowptr[N_NODES + 1];
__device__ int    g_cnt [N_NODES];
__device__ int    g_woff[N_NODES];
__device__ int    g_srcs[TOTE];
__device__ int    g_part [128];
__device__ int    g_part2[128];
__device__ int    g_is64;
__device__ unsigned g_gmax1[8];
__device__ unsigned g_gmax2;

// ---------------- helpers ----------------
__device__ __forceinline__ float leaky02(float x) { return fmaxf(x, 0.2f * x); }

__device__ __forceinline__ long long load_idx(const void* p, long long i, int is64) {
    return is64 ? ((const long long*)p)[i] : (long long)((const int*)p)[i];
}

__device__ __forceinline__ unsigned long long pack2(float x, float y) {
    unsigned long long r;
    asm("mov.b64 %0,{%1,%2};" : "=l"(r) : "f"(x), "f"(y));
    return r;
}
__device__ __forceinline__ void fma2(unsigned long long& d, unsigned long long a, unsigned long long b) {
    asm("fma.rn.f32x2 %0,%1,%2,%0;" : "+l"(d) : "l"(a), "l"(b));
}
__device__ __forceinline__ float2 unpack2(unsigned long long v) {
    float2 f;
    asm("mov.b64 {%0,%1},%2;" : "=f"(f.x), "=f"(f.y) : "l"(v));
    return f;
}

// order-preserving float<->uint encoding (for atomicMax on floats)
__device__ __forceinline__ unsigned fenc(float f) {
    unsigned u = __float_as_uint(f);
    return (u & 0x80000000u) ? ~u : (u | 0x80000000u);
}
__device__ __forceinline__ float fdec(unsigned u) {
    return __uint_as_float((u & 0x80000000u) ? (u & 0x7FFFFFFFu) : ~u);
}
#define ENC_NEG_INF 0x007FFFFFu   // fenc(-inf)

// ---------------- dtype probe + per-call resets ----------------
__global__ void probe_k(const void* ei) {
    __shared__ int s_bad;
    if (threadIdx.x < 8)  g_gmax1[threadIdx.x] = ENC_NEG_INF;
    if (threadIdx.x == 8) g_gmax2 = ENC_NEG_INF;
    if (threadIdx.x == 0) s_bad = 0;
    __syncthreads();
    const long long* p = (const long long*)ei;
    for (int i = threadIdx.x; i < 1024; i += blockDim.x) {
        long long v = p[i];
        if ((v >> 32) != 0) s_bad = 1;
    }
    __syncthreads();
    if (threadIdx.x == 0) g_is64 = (s_bad == 0) ? 1 : 0;
}

// ---------------- GEMM1 + fused attn coefs (scalar f32x2, proven 191us) ----------------
#define MT 256
#define BK 16

__device__ __forceinline__ void g1_load(const float* __restrict__ X, int m0, int k0,
                                        int lrow0, int lh, const float* __restrict__ W,
                                        int tid, float4 ra[2][2], float4& rb) {
#pragma unroll
    for (int s = 0; s < 2; s++) {
        int row = lrow0 + s * 128;
        int gm  = m0 + row;
        if (gm < N_NODES) {
            const float4* p = (const float4*)(X + (size_t)gm * F_IN + k0 + lh);
            ra[s][0] = p[0];
            ra[s][1] = p[1];
        } else {
            ra[s][0] = make_float4(0.f, 0.f, 0.f, 0.f);
            ra[s][1] = make_float4(0.f, 0.f, 0.f, 0.f);
        }
    }
    rb = *(const float4*)(W + (size_t)(k0 + (tid >> 4)) * 64 + (tid & 15) * 4);
}

__device__ __forceinline__ void g1_store(float As[BK][MT], float Bs[BK][64],
                                         int lrow0, int lh, int tid,
                                         const float4 ra[2][2], const float4& rb) {
#pragma unroll
    for (int s = 0; s < 2; s++) {
        int row = lrow0 + s * 128;
        const float* f = (const float*)&ra[s][0];
#pragma unroll
        for (int j = 0; j < 8; j++) {
            int k = lh + j;
            As[k][row ^ ((2 * k) & 31)] = f[j];
        }
    }
    *(float4*)&Bs[tid >> 4][(tid & 15) * 4] = rb;
}

__global__ __launch_bounds__(256, 2) void gemm1_k(const float* __restrict__ X,
                                                  const float* __restrict__ W,
                                                  const float* __restrict__ asw,
                                                  const float* __restrict__ adw) {
    __shared__ float As[2][BK][MT];
    __shared__ float Bs[2][BK][64];
    const int tid = threadIdx.x;
    const int m0  = blockIdx.x * MT;
    const int tx  = tid & 7;
    const int ty8 = (tid >> 3) * 8;
    const int lrow0 = tid >> 1;
    const int lh    = (tid & 1) * 8;

    unsigned long long acc[4][8];
#pragma unroll
    for (int p = 0; p < 4; p++)
#pragma unroll
        for (int j = 0; j < 8; j++) acc[p][j] = 0ull;

    {
        float4 ra[2][2]; float4 rb;
        g1_load(X, m0, 0, lrow0, lh, W, tid, ra, rb);
        g1_store(As[0], Bs[0], lrow0, lh, tid, ra, rb);
    }
    __syncthreads();

    const int NT = F_IN / BK;
    for (int kt = 0; kt < NT; kt++) {
        const int cur = kt & 1;
        float4 ra[2][2]; float4 rb;
        const bool more = (kt + 1) < NT;
        if (more) g1_load(X, m0, (kt + 1) * BK, lrow0, lh, W, tid, ra, rb);

#pragma unroll
        for (int kk = 0; kk < BK; kk++) {
            const int swz = (2 * kk) & 31;
            unsigned long long a[4];
#pragma unroll
            for (int p = 0; p < 4; p++)
                a[p] = *(const unsigned long long*)&As[cur][kk][(ty8 + 2 * p) ^ swz];
            float4 u0 = *(const float4*)&Bs[cur][kk][tx * 8];
            float4 u1 = *(const float4*)&Bs[cur][kk][tx * 8 + 4];
            const float bj[8] = {u0.x, u0.y, u0.z, u0.w, u1.x, u1.y, u1.z, u1.w};
#pragma unroll
            for (int j = 0; j < 8; j++) {
                unsigned long long bb = pack2(bj[j], bj[j]);
#pragma unroll
                for (int p = 0; p < 4; p++) fma2(acc[p][j], a[p], bb);
            }
        }
        if (more) g1_store(As[cur ^ 1], Bs[cur ^ 1], lrow0, lh, tid, ra, rb);
        __syncthreads();
    }

    float sa[8], da[8];
#pragma unroll
    for (int j = 0; j < 8; j++) {
        sa[j] = __ldg(asw + tx * 8 + j);
        da[j] = __ldg(adw + tx * 8 + j);
    }
#pragma unroll
    for (int p = 0; p < 4; p++) {
        float2 f[8];
#pragma unroll
        for (int j = 0; j < 8; j++) f[j] = unpack2(acc[p][j]);
#pragma unroll
        for (int e = 0; e < 2; e++) {
            int gm = m0 + ty8 + 2 * p + e;
            if (gm < N_NODES) {
                float o[8];
#pragma unroll
                for (int j = 0; j < 8; j++) o[j] = e ? f[j].y : f[j].x;
                union { __half2 h[4]; float4 f4; } u;
#pragma unroll
                for (int q = 0; q < 4; q++)
                    u.h[q] = __floats2half2_rn(o[2 * q], o[2 * q + 1]);
                *(float4*)(g_h1 + (size_t)gm * C1 + tx * 8) = u.f4;
                float sv = 0.f, dv = 0.f;
#pragma unroll
                for (int j = 0; j < 8; j++) { sv += o[j] * sa[j]; dv += o[j] * da[j]; }
                g_as1[(size_t)gm * 8 + tx] = sv;
                g_ad1[(size_t)gm * 8 + tx] = dv;
            }
        }
    }
}

// ---------------- global per-head max of a_s (layer 1) ----------------
__global__ void max1_k() {
    const int t      = blockIdx.x * blockDim.x + threadIdx.x;
    const int stride = gridDim.x * blockDim.x;   // multiple of 8
    float mx = -1e30f;
    for (int i = t; i < N_NODES * HEADS; i += stride)
        mx = fmaxf(mx, g_as1[i]);
    // lanes sharing h-class: lane, lane^8, lane^16, lane^24
    mx = fmaxf(mx, __shfl_xor_sync(0xffffffffu, mx, 8));
    mx = fmaxf(mx, __shfl_xor_sync(0xffffffffu, mx, 16));
    const int lane = threadIdx.x & 31;
    if (lane < 8) atomicMax(&g_gmax1[lane], fenc(mx));
}

// ---------------- global max of a_s (layer 2) ----------------
__global__ void max2_k() {
    const int t      = blockIdx.x * blockDim.x + threadIdx.x;
    const int stride = gridDim.x * blockDim.x;
    float mx = -1e30f;
    for (int i = t; i < N_NODES; i += stride)
        mx = fmaxf(mx, g_as2[i]);
#pragma unroll
    for (int o = 16; o; o >>= 1)
        mx = fmaxf(mx, __shfl_xor_sync(0xffffffffu, mx, o));
    if ((threadIdx.x & 31) == 0) atomicMax(&g_gmax2, fenc(mx));
}

// ---------------- CSR build ----------------
__global__ void initcnt_k() {
    int n = blockIdx.x * blockDim.x + threadIdx.x;
    if (n < N_NODES) g_cnt[n] = 1;
}

__global__ void count_k(const void* ei) {
    long long e = (long long)blockIdx.x * blockDim.x + threadIdx.x;
    if (e >= N_EDGES) return;
    int d = (int)load_idx(ei, (long long)N_EDGES + e, g_is64);
    atomicAdd(&g_cnt[d], 1);
}

__global__ void scan1_k() {
    __shared__ int ws[32];
    const int b = blockIdx.x, t = threadIdx.x;
    const int i = b * 1024 + t;
    int v = (i < N_NODES) ? g_cnt[i] : 0;
    const int lane = t & 31, w = t >> 5;
    int x = v;
#pragma unroll
    for (int o = 1; o < 32; o <<= 1) {
        int y = __shfl_up_sync(0xffffffffu, x, o);
        if (lane >= o) x += y;
    }
    if (lane == 31) ws[w] = x;
    __syncthreads();
    if (w == 0) {
        int y = ws[lane];
#pragma unroll
        for (int o = 1; o < 32; o <<= 1) {
            int z = __shfl_up_sync(0xffffffffu, y, o);
            if (lane >= o) y += z;
        }
        ws[lane] = y;
    }
    __syncthreads();
    int off  = (w > 0) ? ws[w - 1] : 0;
    int incl = x + off;
    if (i < N_NODES) g_rowptr[i] = incl - v;
    if (t == 1023) g_part[b] = incl;
}

__global__ void scan2_k() {
    __shared__ int buf[128];
    int t = threadIdx.x;
    buf[t] = (t < NB1024) ? g_part[t] : 0;
    __syncthreads();
#pragma unroll
    for (int o = 1; o < 128; o <<= 1) {
        int y = (t >= o) ? buf[t - o] : 0;
        __syncthreads();
        buf[t] += y;
        __syncthreads();
    }
    g_part2[t] = buf[t];
}

__global__ void scan3_selfloop_k() {
    int b = blockIdx.x, i = b * 1024 + threadIdx.x;
    if (i == 0) g_rowptr[N_NODES] = TOTE;
    if (i >= N_NODES) return;
    int off = (b > 0) ? g_part2[b - 1] : 0;
    int p = g_rowptr[i] + off;
    g_rowptr[i] = p;
    g_srcs[p]   = i;
    g_woff[i]   = p + 1;
}

__global__ void scatter_k(const void* ei) {
    long long e = (long long)blockIdx.x * blockDim.x + threadIdx.x;
    if (e >= N_EDGES) return;
    int is64 = g_is64;
    int s = (int)load_idx(ei, e, is64);
    int d = (int)load_idx(ei, (long long)N_EDGES + e, is64);
    int pos = atomicAdd(&g_woff[d], 1);
    g_srcs[pos] = s;
}

// ---------------- layer1 aggregate: SINGLE PASS (global-max softmax) ----------------
__global__ void agg1_k(const float* __restrict__ b1) {
    const int gw   = (blockIdx.x * blockDim.x + threadIdx.x) >> 5;
    const int lane = threadIdx.x & 31;
    const int w    = threadIdx.x >> 5;
    __shared__ float sAl [8][8][32];
    __shared__ int   sSrc[8][32];
    if (gw >= N_NODES) return;
    const int beg = g_rowptr[gw], end = g_rowptr[gw + 1];

    float ad[8], mh[8];
    {
        float4 u = *(const float4*)(g_ad1 + (size_t)gw * 8);
        float4 v = *(const float4*)(g_ad1 + (size_t)gw * 8 + 4);
        ad[0]=u.x; ad[1]=u.y; ad[2]=u.z; ad[3]=u.w;
        ad[4]=v.x; ad[5]=v.y; ad[6]=v.z; ad[7]=v.w;
    }
#pragma unroll
    for (int h = 0; h < 8; h++)
        mh[h] = leaky02(fdec(g_gmax1[h]) + ad[h]);   // >= all edge logits

    const int c0 = lane * 2;
    const int hd = lane >> 2;
    float ws[8];
#pragma unroll
    for (int h = 0; h < 8; h++) ws[h] = 0.f;
    float a0 = 0.f, a1 = 0.f;

    for (int chunk = beg; chunk < end; chunk += 32) {
        int i = chunk + lane;
        int sx = gw;
        float e8[8];
        if (i < end) {
            sx = g_srcs[i];
            float4 u = *(const float4*)(g_as1 + (size_t)sx * 8);
            float4 v = *(const float4*)(g_as1 + (size_t)sx * 8 + 4);
            float xs[8] = {u.x, u.y, u.z, u.w, v.x, v.y, v.z, v.w};
#pragma unroll
            for (int h = 0; h < 8; h++) {
                e8[h] = __expf(leaky02(xs[h] + ad[h]) - mh[h]);
                ws[h] += e8[h];
            }
        } else {
#pragma unroll
            for (int h = 0; h < 8; h++) e8[h] = 0.f;
        }
        sSrc[w][lane] = sx;
#pragma unroll
        for (int h = 0; h < 8; h++) sAl[w][h][lane] = e8[h];
        __syncwarp();

        const int ec = min(32, end - chunk);
#pragma unroll 8
        for (int e = 0; e < ec; e++) {
            int   sy = sSrc[w][e];
            float al = sAl[w][hd][e];
            float2 hv = __half22float2(*(const __half2*)(g_h1 + (size_t)sy * C1 + c0));
            a0 += hv.x * al;
            a1 += hv.y * al;
        }
        __syncwarp();
    }

    // reduce weight sums across lanes (all lanes end with identical ws[h])
#pragma unroll
    for (int o = 16; o; o >>= 1)
#pragma unroll
        for (int h = 0; h < 8; h++)
            ws[h] += __shfl_xor_sync(0xffffffffu, ws[h], o);

    const float rsh = 1.0f / ws[hd];
    float o0 = a0 * rsh + b1[c0];
    float o1 = a1 * rsh + b1[c0 + 1];
    g_hact[(size_t)gw * C1 + c0]     = (o0 > 0.f) ? o0 : (__expf(o0) - 1.0f);
    g_hact[(size_t)gw * C1 + c0 + 1] = (o1 > 0.f) ? o1 : (__expf(o1) - 1.0f);
}

// ---------------- layer2 GEMM + attn coefs ----------------
__global__ void gemm2_attn_k(const float* __restrict__ W2,
                             const float* __restrict__ asrc2,
                             const float* __restrict__ adst2) {
    __shared__ float Xs[16 * 64];
    __shared__ float Ws[64 * 16];
    const int tid = threadIdx.x;
    const int n0  = blockIdx.x * 16;

    ((float4*)Ws)[tid] = ((const float4*)W2)[tid];
    {
        int row = tid >> 4;
        float4 v = make_float4(0.f, 0.f, 0.f, 0.f);
        if (n0 + row < N_NODES)
            v = ((const float4*)(g_hact + (size_t)n0 * C1))[tid];
        ((float4*)Xs)[tid] = v;
    }
    __syncthreads();

    const int r = tid >> 4, c = tid & 15;
    float acc = 0.f;
#pragma unroll
    for (int k = 0; k < 64; k++) acc += Xs[r * 64 + k] * Ws[k * 16 + c];
    const int n = n0 + r;
    if (n < N_NODES) g_h2[(size_t)n * NCLS + c] = __float2half_rn(acc);

    float vs = acc * asrc2[c];
    float vd = acc * adst2[c];
#pragma unroll
    for (int off = 8; off; off >>= 1) {
        vs += __shfl_xor_sync(0xffffffffu, vs, off);
        vd += __shfl_xor_sync(0xffffffffu, vd, off);
    }
    if (c == 0 && n < N_NODES) {
        g_as2[n] = vs;
        g_ad2[n] = vd;
    }
}

// ---------------- layer2 aggregate: SINGLE PASS ----------------
__global__ void agg2_k(const float* __restrict__ b2, float* __restrict__ out) {
    const int gw   = (blockIdx.x * blockDim.x + threadIdx.x) >> 5;
    const int lane = threadIdx.x & 31;
    const int w    = threadIdx.x >> 5;
    __shared__ float sAl [8][32];
    __shared__ int   sSrc[8][32];
    if (gw >= N_NODES) return;
    const int beg = g_rowptr[gw], end = g_rowptr[gw + 1];
    const float adn = g_ad2[gw];
    const float mh  = leaky02(fdec(g_gmax2) + adn);

    const int c    = lane & 15;
    const int half = lane >> 4;
    float acc = 0.f, ws = 0.f;

    for (int chunk = beg; chunk < end; chunk += 32) {
        int i = chunk + lane;
        int sx = gw;
        float e = 0.f;
        if (i < end) {
            sx = g_srcs[i];
            e  = __expf(leaky02(g_as2[sx] + adn) - mh);
            ws += e;
        }
        sSrc[w][lane] = sx;
        sAl [w][lane] = e;
        __syncwarp();

        const int ec = min(32, end - chunk);
#pragma unroll 8
        for (int e0 = half; e0 < ec; e0 += 2) {
            int   sy = sSrc[w][e0];
            float al = sAl[w][e0];
            acc += __half2float(g_h2[(size_t)sy * NCLS + c]) * al;
        }
        __syncwarp();
    }

#pragma unroll
    for (int o = 16; o; o >>= 1)
        ws += __shfl_xor_sync(0xffffffffu, ws, o);
    const float rs = 1.0f / ws;

    acc += __shfl_down_sync(0xffffffffu, acc, 16);
    if (lane < 16) out[(size_t)gw * NCLS + c] = acc * rs + b2[c];
}

// ---------------- launch ----------------
extern "C" void kernel_launch(void* const* d_in, const int* in_sizes, int n_in,
                              void* d_out, int out_size) {
    const float* x    = (const float*)d_in[0];
    const void*  ei   = d_in[1];
    const float* W1   = (const float*)d_in[2];
    const float* as1w = (const float*)d_in[3];
    const float* ad1w = (const float*)d_in[4];
    const float* b1   = (const float*)d_in[5];
    const float* W2   = (const float*)d_in[6];
    const float* as2w = (const float*)d_in[7];
    const float* ad2w = (const float*)d_in[8];
    const float* b2   = (const float*)d_in[9];
    float* out = (float*)d_out;

    probe_k<<<1, 256>>>(ei);
    initcnt_k<<<(N_NODES + 255) / 256, 256>>>();
    count_k<<<(N_EDGES + 255) / 256, 256>>>(ei);
    // launch index 3 -> ncu capture slot
    gemm1_k<<<(N_NODES + MT - 1) / MT, 256>>>(x, W1, as1w, ad1w);

    scan1_k<<<NB1024, 1024>>>();
    scan2_k<<<1, 128>>>();
    scan3_selfloop_k<<<NB1024, 1024>>>();
    scatter_k<<<(N_EDGES + 255) / 256, 256>>>(ei);
    max1_k<<<128, 256>>>();

    agg1_k<<<(N_NODES + 7) / 8, 256>>>(b1);
    gemm2_attn_k<<<(N_NODES + 15) / 16, 256>>>(W2, as2w, ad2w);
    max2_k<<<128, 256>>>();
    agg2_k<<<(N_NODES + 7) / 8, 256>>>(b2, out);
}